// round 2
// baseline (speedup 1.0000x reference)
#include <cuda_runtime.h>
#include <cuda_bf16.h>
#include <cstdint>

#define NUM_OBS 100000
#define NUM_ACT 10
#define RD 64
#define MAXB 8192
#define BM 128
#define BN 128

// Scratch for gathered + hi/lo-split operands (4 MB total). Device globals are
// the sanctioned scratch mechanism (no allocations allowed).
__device__ __nv_bfloat16 g_Fhi[MAXB * RD];
__device__ __nv_bfloat16 g_Flo[MAXB * RD];
__device__ __nv_bfloat16 g_Bhi[MAXB * RD];
__device__ __nv_bfloat16 g_Blo[MAXB * RD];

__device__ __forceinline__ int clampi(int v, int lo, int hi) {
    return v < lo ? lo : (v > hi ? hi : v);
}

// One block per batch row; 64 threads = one per repr dim.
// Gathers W_f[fwd_idx] / W_b[bwd_idx] and splits each fp32 into bf16 hi + lo.
__global__ void gather_split_kernel(
    const int* __restrict__ obs, const int* __restrict__ act,
    const int* __restrict__ fobs, const int* __restrict__ fact,
    const float* __restrict__ Wf, const float* __restrict__ Wb,
    int Btot)
{
    int i = blockIdx.x;
    int k = threadIdx.x;
    if (i >= Btot) return;

    {
        int o = clampi(obs[i], 0, NUM_OBS - 1);
        int a = clampi(act[i], 0, NUM_ACT - 1);
        long long idx = (long long)o * NUM_ACT + a;
        float x = Wf[idx * RD + k];
        __nv_bfloat16 hi = __float2bfloat16(x);
        float lo = x - __bfloat162float(hi);
        g_Fhi[i * RD + k] = hi;
        g_Flo[i * RD + k] = __float2bfloat16(lo);
    }
    {
        int o = clampi(fobs[i], 0, NUM_OBS - 1);
        int a = clampi(fact[i], 0, NUM_ACT - 1);
        long long idx = (long long)o * NUM_ACT + a;
        float x = Wb[idx * RD + k];
        __nv_bfloat16 hi = __float2bfloat16(x);
        float lo = x - __bfloat162float(hi);
        g_Bhi[i * RD + k] = hi;
        g_Blo[i * RD + k] = __float2bfloat16(lo);
    }
}

__device__ __forceinline__ void ldsm_x4(uint32_t& r0, uint32_t& r1,
                                        uint32_t& r2, uint32_t& r3,
                                        uint32_t addr)
{
    asm volatile(
        "ldmatrix.sync.aligned.m8n8.x4.shared.b16 {%0,%1,%2,%3}, [%4];"
        : "=r"(r0), "=r"(r1), "=r"(r2), "=r"(r3)
        : "r"(addr));
}

__device__ __forceinline__ void mma16816(float* c, const uint32_t* a,
                                         const uint32_t* b)
{
    asm volatile(
        "mma.sync.aligned.m16n8k16.row.col.f32.bf16.bf16.f32 "
        "{%0,%1,%2,%3}, {%4,%5,%6,%7}, {%8,%9}, {%0,%1,%2,%3};"
        : "+f"(c[0]), "+f"(c[1]), "+f"(c[2]), "+f"(c[3])
        : "r"(a[0]), "r"(a[1]), "r"(a[2]), "r"(a[3]),
          "r"(b[0]), "r"(b[1]));
}

// out[i][j] = F[i] . B[j], computed as hi*hi + hi*lo + lo*hi in bf16 MMAs
// with fp32 accumulation (lo*lo term ~2^-18 relative; dropped).
// CTA tile 128x128, 8 warps of 64(M)x32(N), K=64 resident in smem.
__global__ void __launch_bounds__(256, 2) fb_gemm_kernel(
    float* __restrict__ out, int Btot)
{
    extern __shared__ __align__(16) uint8_t smem[];
    // smem layout (each 128 rows x 64 bf16 = 128 B/row = 16 KB):
    //   [0      ,16384) A_hi   [16384,32768) A_lo
    //   [32768  ,49152) B_hi   [49152,65536) B_lo
    const int tid = threadIdx.x;
    const int tileM = blockIdx.y * BM;
    const int tileN = blockIdx.x * BN;

    // ---- fill smem (SW128 swizzle: 16B chunk index XOR (row&7)) ----
    {
        const __nv_bfloat16* srcs[4] = { g_Fhi, g_Flo, g_Bhi, g_Blo };
        const int bases[4] = { tileM, tileM, tileN, tileN };
#pragma unroll
        for (int buf = 0; buf < 4; buf++) {
            const uint4* src = (const uint4*)srcs[buf];  // 8 uint4 per row
            uint4* dst = (uint4*)(smem + buf * 16384);
#pragma unroll
            for (int it = 0; it < 4; it++) {
                int t = tid + it * 256;
                int row = t >> 3;
                int ch = t & 7;
                int grow = bases[buf] + row;
                uint4 v = make_uint4(0u, 0u, 0u, 0u);
                if (grow < Btot) v = src[grow * 8 + ch];
                dst[row * 8 + (ch ^ (row & 7))] = v;
            }
        }
    }
    __syncthreads();

    const int wid = tid >> 5, lane = tid & 31;
    const int warp_m = wid & 1;   // 2 warps over M
    const int warp_n = wid >> 1;  // 4 warps over N
    const int m0w = warp_m * 64;
    const int n0w = warp_n * 32;

    // ldmatrix per-lane addressing: lanes in 4 groups of 8.
    const int lr = lane & 7;
    const int lq = lane >> 3;
    const int row_add = lr + (lq & 1) * 8;   // +8 rows for groups 1,3
    const int kb_add = (lq >> 1) * 16;       // +16 B (k+8) for groups 2,3
    const int swz = lr << 4;                 // SW128 xor (row&7)<<4 == lr<<4

    uint32_t smem_u = (uint32_t)__cvta_generic_to_shared(smem);

    float c[4][4][4];
#pragma unroll
    for (int mf = 0; mf < 4; mf++)
#pragma unroll
        for (int nf = 0; nf < 4; nf++)
#pragma unroll
            for (int r = 0; r < 4; r++) c[mf][nf][r] = 0.0f;

    const uint32_t aoff[3] = { 0u, 0u, 16384u };       // hi, hi, lo
    const uint32_t boff[3] = { 32768u, 49152u, 32768u }; // hi, lo, hi

#pragma unroll
    for (int t = 0; t < 3; t++) {
        uint32_t baseA = smem_u + aoff[t];
        uint32_t baseB = smem_u + boff[t];
#pragma unroll
        for (int ks = 0; ks < 4; ks++) {
            int kb = ks * 32;  // byte offset within 128 B row
            uint32_t a[4][4];
#pragma unroll
            for (int mf = 0; mf < 4; mf++) {
                int row = m0w + mf * 16 + row_add;
                uint32_t addr = baseA + row * 128 + ((kb + kb_add) ^ swz);
                ldsm_x4(a[mf][0], a[mf][1], a[mf][2], a[mf][3], addr);
            }
            uint32_t b[4][2];
#pragma unroll
            for (int nh = 0; nh < 2; nh++) {
                int row = n0w + nh * 16 + row_add;
                uint32_t addr = baseB + row * 128 + ((kb + kb_add) ^ swz);
                uint32_t r0, r1, r2, r3;
                ldsm_x4(r0, r1, r2, r3, addr);
                b[nh * 2 + 0][0] = r0;
                b[nh * 2 + 1][0] = r1;
                b[nh * 2 + 0][1] = r2;
                b[nh * 2 + 1][1] = r3;
            }
#pragma unroll
            for (int mf = 0; mf < 4; mf++)
#pragma unroll
                for (int nf = 0; nf < 4; nf++)
                    mma16816(c[mf][nf], a[mf], b[nf]);
        }
    }

    // ---- epilogue: STG.64 of (c0,c1) and (c2,c3) pairs ----
    const int gid = lane >> 2, qid = lane & 3;
#pragma unroll
    for (int mf = 0; mf < 4; mf++) {
        int rg = tileM + m0w + mf * 16 + gid;
#pragma unroll
        for (int nf = 0; nf < 4; nf++) {
            int cg = tileN + n0w + nf * 8 + qid * 2;
            if (cg + 1 < Btot) {
                if (rg < Btot) {
                    float2 v = make_float2(c[mf][nf][0], c[mf][nf][1]);
                    *(float2*)(out + (size_t)rg * Btot + cg) = v;
                }
                if (rg + 8 < Btot) {
                    float2 v = make_float2(c[mf][nf][2], c[mf][nf][3]);
                    *(float2*)(out + (size_t)(rg + 8) * Btot + cg) = v;
                }
            }
        }
    }
}

extern "C" void kernel_launch(void* const* d_in, const int* in_sizes, int n_in,
                              void* d_out, int out_size)
{
    const int* obs  = (const int*)d_in[0];
    const int* act  = (const int*)d_in[1];
    const int* fobs = (const int*)d_in[2];
    const int* fact = (const int*)d_in[3];
    const float* Wf = (const float*)d_in[4];
    const float* Wb = (const float*)d_in[5];
    float* out = (float*)d_out;
    int Btot = in_sizes[0];

    gather_split_kernel<<<Btot, RD>>>(obs, act, fobs, fact, Wf, Wb, Btot);

    cudaFuncSetAttribute(fb_gemm_kernel,
                         cudaFuncAttributeMaxDynamicSharedMemorySize, 65536);
    dim3 grid((Btot + BN - 1) / BN, (Btot + BM - 1) / BM);
    fb_gemm_kernel<<<grid, 256, 65536>>>(out, Btot);
}

// round 7
// speedup vs baseline: 1.7220x; 1.7220x over previous
#include <cuda_runtime.h>
#include <cuda_fp16.h>
#include <cstdint>

#define NUM_OBS 100000
#define NUM_ACT 10
#define RD 64
#define MAXB 8192
#define BM 128
#define BN 128
#define THREADS 256
#define OFF_A 0
#define OFF_B 16384
#define CSTRIDE 136   // staged-C row stride in floats (128 + 8 pad -> 8-bank/row shift)
#define SMEM_BYTES (128 * CSTRIDE * 4)  // 69632 B; operands occupy first 32 KB

// Gathered fp16 operands (2 MB). Device globals = sanctioned scratch.
__device__ __half g_F16[MAXB * RD];
__device__ __half g_B16[MAXB * RD];

__device__ __forceinline__ int clampi(int v, int lo, int hi) {
    return v < lo ? lo : (v > hi ? hi : v);
}

// 4 batch rows per 256-thread block: gather W rows, round fp32 -> fp16.
__global__ void gather_kernel(
    const int* __restrict__ obs, const int* __restrict__ act,
    const int* __restrict__ fobs, const int* __restrict__ fact,
    const float* __restrict__ Wf, const float* __restrict__ Wb,
    int Btot)
{
    int i = blockIdx.x * 4 + (threadIdx.x >> 6);
    int k = threadIdx.x & 63;
    if (i >= Btot) return;
    {
        int o = clampi(obs[i], 0, NUM_OBS - 1);
        int a = clampi(act[i], 0, NUM_ACT - 1);
        long long idx = (long long)o * NUM_ACT + a;
        g_F16[i * RD + k] = __float2half_rn(Wf[idx * RD + k]);
    }
    {
        int o = clampi(fobs[i], 0, NUM_OBS - 1);
        int a = clampi(fact[i], 0, NUM_ACT - 1);
        long long idx = (long long)o * NUM_ACT + a;
        g_B16[i * RD + k] = __float2half_rn(Wb[idx * RD + k]);
    }
}

__device__ __forceinline__ uint32_t smem_u32(const void* p) {
    uint32_t a;
    asm("{ .reg .u64 t; cvta.to.shared.u64 t, %1; cvt.u32.u64 %0, t; }"
        : "=r"(a) : "l"(p));
    return a;
}

__device__ __forceinline__ void cp_async16(uint32_t dst, const void* src) {
    asm volatile("cp.async.cg.shared.global [%0], [%1], 16;"
                 :: "r"(dst), "l"(src));
}

__device__ __forceinline__ void ldsm_x4(uint32_t& r0, uint32_t& r1,
                                        uint32_t& r2, uint32_t& r3,
                                        uint32_t addr)
{
    asm volatile(
        "ldmatrix.sync.aligned.m8n8.x4.shared.b16 {%0,%1,%2,%3}, [%4];"
        : "=r"(r0), "=r"(r1), "=r"(r2), "=r"(r3)
        : "r"(addr));
}

__device__ __forceinline__ void mma16816_f16(float* c, const uint32_t* a,
                                             const uint32_t* b)
{
    asm volatile(
        "mma.sync.aligned.m16n8k16.row.col.f32.f16.f16.f32 "
        "{%0,%1,%2,%3}, {%4,%5,%6,%7}, {%8,%9}, {%0,%1,%2,%3};"
        : "+f"(c[0]), "+f"(c[1]), "+f"(c[2]), "+f"(c[3])
        : "r"(a[0]), "r"(a[1]), "r"(a[2]), "r"(a[3]),
          "r"(b[0]), "r"(b[1]));
}

// out[i][j] = F[i].B[j], single-pass fp16 HMMA, fp32 accumulation.
// CTA tile 128x128, 8 warps of 64(M)x32(N), K=64 resident in smem.
// Epilogue stages C through smem for fully coalesced STG.128.
__global__ void __launch_bounds__(THREADS, 2) fb_gemm_kernel(
    float* __restrict__ out, int Btot)
{
    extern __shared__ __align__(16) uint8_t smem[];
    const uint32_t sbase = smem_u32(smem);
    const int tid = threadIdx.x;
    const int tileM = blockIdx.y * BM;
    const int tileN = blockIdx.x * BN;

    // ---- fill smem via cp.async (SW128 swizzle: 16B chunk ^ (row&7)) ----
    {
        const uint4* srcA = (const uint4*)g_F16;  // 8 uint4 per 64-half row
        const uint4* srcB = (const uint4*)g_B16;
#pragma unroll
        for (int it = 0; it < 4; it++) {
            int t = tid + it * THREADS;       // 0..1023
            int r = t >> 3, ch = t & 7;
            uint32_t soff = r * 128 + ((ch ^ (r & 7)) << 4);
            int ga = tileM + r, gb = tileN + r;
            if (ga < Btot) cp_async16(sbase + OFF_A + soff, srcA + ga * 8 + ch);
            else *(uint4*)(smem + OFF_A + soff) = make_uint4(0u, 0u, 0u, 0u);
            if (gb < Btot) cp_async16(sbase + OFF_B + soff, srcB + gb * 8 + ch);
            else *(uint4*)(smem + OFF_B + soff) = make_uint4(0u, 0u, 0u, 0u);
        }
        asm volatile("cp.async.commit_group;");
        asm volatile("cp.async.wait_group 0;");
    }
    __syncthreads();

    const int wid = tid >> 5, lane = tid & 31;
    const int m0w = (wid & 1) * 64;   // 2 warps over M
    const int n0w = (wid >> 1) * 32;  // 4 warps over N

    // ldmatrix per-lane addressing: lanes in 4 groups of 8.
    const int lr = lane & 7;
    const int lq = lane >> 3;
    const int row_add = lr + (lq & 1) * 8;   // +8 rows for groups 1,3
    const int kb_add = (lq >> 1) * 16;       // +16 B (k+8) for groups 2,3
    const int swz = lr << 4;                 // SW128 xor: (row&7)<<4 == lr<<4

    float c[4][4][4];
#pragma unroll
    for (int mf = 0; mf < 4; mf++)
#pragma unroll
        for (int nf = 0; nf < 4; nf++)
#pragma unroll
            for (int r = 0; r < 4; r++) c[mf][nf][r] = 0.0f;

#pragma unroll
    for (int ks = 0; ks < 4; ks++) {
        int kb = ks * 32;  // byte offset within 128 B row
        uint32_t a[4][4];
#pragma unroll
        for (int mf = 0; mf < 4; mf++) {
            int row = m0w + mf * 16 + row_add;
            uint32_t addr = sbase + OFF_A + row * 128 + ((kb + kb_add) ^ swz);
            ldsm_x4(a[mf][0], a[mf][1], a[mf][2], a[mf][3], addr);
        }
        uint32_t b[4][2];
#pragma unroll
        for (int nh = 0; nh < 2; nh++) {
            int row = n0w + nh * 16 + row_add;
            uint32_t addr = sbase + OFF_B + row * 128 + ((kb + kb_add) ^ swz);
            uint32_t r0, r1, r2, r3;
            ldsm_x4(r0, r1, r2, r3, addr);
            b[nh * 2 + 0][0] = r0;
            b[nh * 2 + 1][0] = r1;
            b[nh * 2 + 0][1] = r2;
            b[nh * 2 + 1][1] = r3;
        }
#pragma unroll
        for (int mf = 0; mf < 4; mf++)
#pragma unroll
            for (int nf = 0; nf < 4; nf++)
                mma16816_f16(c[mf][nf], a[mf], b[nf]);
    }

    // ---- epilogue: stage C in smem (row stride 136 floats -> conflict-free),
    //      then fully coalesced STG.128 rows ----
    __syncthreads();  // all warps done reading operand smem
    {
        float* cs = (float*)smem;
        const int gid = lane >> 2, qid = lane & 3;
#pragma unroll
        for (int mf = 0; mf < 4; mf++) {
            int r0 = m0w + mf * 16 + gid;
#pragma unroll
            for (int nf = 0; nf < 4; nf++) {
                int col = n0w + nf * 8 + qid * 2;
                *(float2*)(cs + r0 * CSTRIDE + col) =
                    make_float2(c[mf][nf][0], c[mf][nf][1]);
                *(float2*)(cs + (r0 + 8) * CSTRIDE + col) =
                    make_float2(c[mf][nf][2], c[mf][nf][3]);
            }
        }
    }
    __syncthreads();
    {
        const float* cs = (const float*)smem;
#pragma unroll
        for (int i = 0; i < 16; i++) {
            int lrow = wid * 16 + i;
            int grow = tileM + lrow;
            if (grow >= Btot) continue;
            float4 v = *(const float4*)(cs + lrow * CSTRIDE + lane * 4);
            int gcol = tileN + lane * 4;
            if (tileN + BN <= Btot) {
                *(float4*)(out + (size_t)grow * Btot + gcol) = v;
            } else {
                float vv[4] = { v.x, v.y, v.z, v.w };
                for (int j = 0; j < 4; j++)
                    if (gcol + j < Btot)
                        out[(size_t)grow * Btot + gcol + j] = vv[j];
            }
        }
    }
}

extern "C" void kernel_launch(void* const* d_in, const int* in_sizes, int n_in,
                              void* d_out, int out_size)
{
    const int* obs  = (const int*)d_in[0];
    const int* act  = (const int*)d_in[1];
    const int* fobs = (const int*)d_in[2];
    const int* fact = (const int*)d_in[3];
    const float* Wf = (const float*)d_in[4];
    const float* Wb = (const float*)d_in[5];
    float* out = (float*)d_out;
    int Btot = in_sizes[0];

    gather_kernel<<<(Btot + 3) / 4, 256>>>(obs, act, fobs, fact, Wf, Wb, Btot);

    cudaFuncSetAttribute(fb_gemm_kernel,
                         cudaFuncAttributeMaxDynamicSharedMemorySize,
                         SMEM_BYTES);
    dim3 grid((Btot + BN - 1) / BN, (Btot + BM - 1) / BM);
    fb_gemm_kernel<<<grid, THREADS, SMEM_BYTES>>>(out, Btot);
}

// round 9
// speedup vs baseline: 1.8920x; 1.0987x over previous
#include <cuda_runtime.h>
#include <cuda_fp16.h>
#include <cstdint>

#define NUM_OBS 100000
#define NUM_ACT 10
#define RD 64
#define MAXB 8192
#define BM 128
#define BN 128
#define THREADS 512
#define OFF_A 0
#define OFF_B 16384
#define OFF_C 32768   // C staging after operands (no reuse -> no extra syncs)
#define CSTRIDE 136   // staged-C row stride in floats (8-bank/row shift)
#define SMEM_BYTES (OFF_C + 128 * CSTRIDE * 4)  // 32KB + 69.6KB = 101.4KB

// Gathered fp16 operands (2 MB). Device globals = sanctioned scratch.
__device__ __half g_F16[MAXB * RD];
__device__ __half g_B16[MAXB * RD];

__device__ __forceinline__ int clampi(int v, int lo, int hi) {
    return v < lo ? lo : (v > hi ? hi : v);
}

// 8 batch rows per 256-thread block; 32 lanes/row, float2 -> half2 per lane.
__global__ void gather_kernel(
    const int* __restrict__ obs, const int* __restrict__ act,
    const int* __restrict__ fobs, const int* __restrict__ fact,
    const float* __restrict__ Wf, const float* __restrict__ Wb,
    int Btot)
{
    int i = blockIdx.x * 8 + (threadIdx.x >> 5);
    int lane = threadIdx.x & 31;
    if (i >= Btot) return;
    {
        int o = clampi(obs[i], 0, NUM_OBS - 1);
        int a = clampi(act[i], 0, NUM_ACT - 1);
        long long idx = (long long)o * NUM_ACT + a;
        float2 v = *(const float2*)(Wf + idx * RD + lane * 2);
        *(__half2*)(g_F16 + i * RD + lane * 2) =
            __floats2half2_rn(v.x, v.y);
    }
    {
        int o = clampi(fobs[i], 0, NUM_OBS - 1);
        int a = clampi(fact[i], 0, NUM_ACT - 1);
        long long idx = (long long)o * NUM_ACT + a;
        float2 v = *(const float2*)(Wb + idx * RD + lane * 2);
        *(__half2*)(g_B16 + i * RD + lane * 2) =
            __floats2half2_rn(v.x, v.y);
    }
}

__device__ __forceinline__ uint32_t smem_u32(const void* p) {
    uint32_t a;
    asm("{ .reg .u64 t; cvta.to.shared.u64 t, %1; cvt.u32.u64 %0, t; }"
        : "=r"(a) : "l"(p));
    return a;
}

__device__ __forceinline__ void cp_async16(uint32_t dst, const void* src) {
    asm volatile("cp.async.cg.shared.global [%0], [%1], 16;"
                 :: "r"(dst), "l"(src));
}

__device__ __forceinline__ void ldsm_x4(uint32_t& r0, uint32_t& r1,
                                        uint32_t& r2, uint32_t& r3,
                                        uint32_t addr)
{
    asm volatile(
        "ldmatrix.sync.aligned.m8n8.x4.shared.b16 {%0,%1,%2,%3}, [%4];"
        : "=r"(r0), "=r"(r1), "=r"(r2), "=r"(r3)
        : "r"(addr));
}

__device__ __forceinline__ void mma16816_f16(float* c, const uint32_t* a,
                                             const uint32_t* b)
{
    asm volatile(
        "mma.sync.aligned.m16n8k16.row.col.f32.f16.f16.f32 "
        "{%0,%1,%2,%3}, {%4,%5,%6,%7}, {%8,%9}, {%0,%1,%2,%3};"
        : "+f"(c[0]), "+f"(c[1]), "+f"(c[2]), "+f"(c[3])
        : "r"(a[0]), "r"(a[1]), "r"(a[2]), "r"(a[3]),
          "r"(b[0]), "r"(b[1]));
}

__device__ __forceinline__ void stg_cs_128(float* p, float4 v) {
    asm volatile("st.global.cs.v4.f32 [%0], {%1,%2,%3,%4};"
                 :: "l"(p), "f"(v.x), "f"(v.y), "f"(v.z), "f"(v.w)
                 : "memory");
}

// out[i][j] = F[i].B[j], single-pass fp16 HMMA, fp32 accumulation.
// CTA 128x128, 16 warps of 32(M)x32(N), K=64 resident in smem.
// Epilogue stages C through smem -> coalesced streaming STG.128.
__global__ void __launch_bounds__(THREADS, 2) fb_gemm_kernel(
    float* __restrict__ out, int Btot)
{
    extern __shared__ __align__(16) uint8_t smem[];
    const uint32_t sbase = smem_u32(smem);
    const int tid = threadIdx.x;
    const int tileM = blockIdx.y * BM;
    const int tileN = blockIdx.x * BN;

    // ---- fill smem via cp.async (SW128 swizzle: 16B chunk ^ (row&7)) ----
    {
        const uint4* srcA = (const uint4*)g_F16;  // 8 uint4 per 64-half row
        const uint4* srcB = (const uint4*)g_B16;
#pragma unroll
        for (int it = 0; it < 2; it++) {
            int t = tid + it * THREADS;       // 0..1023
            int r = t >> 3, ch = t & 7;
            uint32_t soff = r * 128 + ((ch ^ (r & 7)) << 4);
            int ga = tileM + r, gb = tileN + r;
            if (ga < Btot) cp_async16(sbase + OFF_A + soff, srcA + ga * 8 + ch);
            else *(uint4*)(smem + OFF_A + soff) = make_uint4(0u, 0u, 0u, 0u);
            if (gb < Btot) cp_async16(sbase + OFF_B + soff, srcB + gb * 8 + ch);
            else *(uint4*)(smem + OFF_B + soff) = make_uint4(0u, 0u, 0u, 0u);
        }
        asm volatile("cp.async.commit_group;");
        asm volatile("cp.async.wait_group 0;");
    }
    __syncthreads();

    const int wid = tid >> 5, lane = tid & 31;
    const int m0w = (wid & 3) * 32;   // 4 warps over M
    const int n0w = (wid >> 2) * 32;  // 4 warps over N

    // ldmatrix per-lane addressing: lanes in 4 groups of 8.
    const int lr = lane & 7;
    const int lq = lane >> 3;
    const int row_add = lr + (lq & 1) * 8;   // +8 rows for groups 1,3
    const int kb_add = (lq >> 1) * 16;       // +16 B (k+8) for groups 2,3
    const int swz = lr << 4;                 // SW128 xor: (row&7)<<4 == lr<<4

    float c[2][4][4];
#pragma unroll
    for (int mf = 0; mf < 2; mf++)
#pragma unroll
        for (int nf = 0; nf < 4; nf++)
#pragma unroll
            for (int r = 0; r < 4; r++) c[mf][nf][r] = 0.0f;

#pragma unroll
    for (int ks = 0; ks < 4; ks++) {
        int kb = ks * 32;  // byte offset within 128 B row
        uint32_t a[2][4];
#pragma unroll
        for (int mf = 0; mf < 2; mf++) {
            int row = m0w + mf * 16 + row_add;
            uint32_t addr = sbase + OFF_A + row * 128 + ((kb + kb_add) ^ swz);
            ldsm_x4(a[mf][0], a[mf][1], a[mf][2], a[mf][3], addr);
        }
        uint32_t b[4][2];
#pragma unroll
        for (int nh = 0; nh < 2; nh++) {
            int row = n0w + nh * 16 + row_add;
            uint32_t addr = sbase + OFF_B + row * 128 + ((kb + kb_add) ^ swz);
            uint32_t r0, r1, r2, r3;
            ldsm_x4(r0, r1, r2, r3, addr);
            b[nh * 2 + 0][0] = r0;
            b[nh * 2 + 1][0] = r1;
            b[nh * 2 + 0][1] = r2;
            b[nh * 2 + 1][1] = r3;
        }
#pragma unroll
        for (int mf = 0; mf < 2; mf++)
#pragma unroll
            for (int nf = 0; nf < 4; nf++)
                mma16816_f16(c[mf][nf], a[mf], b[nf]);
    }

    // ---- epilogue: stage C in smem, then coalesced streaming STG.128 ----
    {
        float* cs = (float*)(smem + OFF_C);
        const int gid = lane >> 2, qid = lane & 3;
#pragma unroll
        for (int mf = 0; mf < 2; mf++) {
            int r0 = m0w + mf * 16 + gid;
#pragma unroll
            for (int nf = 0; nf < 4; nf++) {
                int col = n0w + nf * 8 + qid * 2;
                *(float2*)(cs + r0 * CSTRIDE + col) =
                    make_float2(c[mf][nf][0], c[mf][nf][1]);
                *(float2*)(cs + (r0 + 8) * CSTRIDE + col) =
                    make_float2(c[mf][nf][2], c[mf][nf][3]);
            }
        }
    }
    __syncthreads();
    {
        const float* cs = (const float*)(smem + OFF_C);
#pragma unroll
        for (int i = 0; i < 8; i++) {
            int lrow = wid * 8 + i;
            int grow = tileM + lrow;
            if (grow >= Btot) continue;
            float4 v = *(const float4*)(cs + lrow * CSTRIDE + lane * 4);
            int gcol = tileN + lane * 4;
            if (tileN + BN <= Btot) {
                stg_cs_128(out + (size_t)grow * Btot + gcol, v);
            } else {
                float vv[4] = { v.x, v.y, v.z, v.w };
                for (int j = 0; j < 4; j++)
                    if (gcol + j < Btot)
                        out[(size_t)grow * Btot + gcol + j] = vv[j];
            }
        }
    }
}

extern "C" void kernel_launch(void* const* d_in, const int* in_sizes, int n_in,
                              void* d_out, int out_size)
{
    const int* obs  = (const int*)d_in[0];
    const int* act  = (const int*)d_in[1];
    const int* fobs = (const int*)d_in[2];
    const int* fact = (const int*)d_in[3];
    const float* Wf = (const float*)d_in[4];
    const float* Wb = (const float*)d_in[5];
    float* out = (float*)d_out;
    int Btot = in_sizes[0];

    gather_kernel<<<(Btot + 7) / 8, 256>>>(obs, act, fobs, fact, Wf, Wb, Btot);

    cudaFuncSetAttribute(fb_gemm_kernel,
                         cudaFuncAttributeMaxDynamicSharedMemorySize,
                         SMEM_BYTES);
    dim3 grid((Btot + BN - 1) / BN, (Btot + BM - 1) / BM);
    fb_gemm_kernel<<<grid, THREADS, SMEM_BYTES>>>(out, Btot);
}

// round 10
// speedup vs baseline: 2.0766x; 1.0976x over previous
#include <cuda_runtime.h>
#include <cuda_fp16.h>
#include <cstdint>

#define NUM_OBS 100000
#define NUM_ACT 10
#define RD 64
#define MAXB 8192
#define BM 64
#define BN 128
#define THREADS 256
#define OFF_A 0
#define OFF_B 8192            // A: 64 rows x 128B = 8KB; B: 128 rows x 128B = 16KB
#define CSTRIDE 136           // staged-C row stride in floats (8-bank/row shift)
#define SMEM_BYTES (BM * CSTRIDE * 4)  // 34816 B; C staging overlays dead operands

// Gathered fp16 operands (2 MB). Device globals = sanctioned scratch.
__device__ __half g_F16[MAXB * RD];
__device__ __half g_B16[MAXB * RD];

__device__ __forceinline__ int clampi(int v, int lo, int hi) {
    return v < lo ? lo : (v > hi ? hi : v);
}

// 8 batch rows per 256-thread block; 32 lanes/row, float2 -> half2 per lane.
__global__ void gather_kernel(
    const int* __restrict__ obs, const int* __restrict__ act,
    const int* __restrict__ fobs, const int* __restrict__ fact,
    const float* __restrict__ Wf, const float* __restrict__ Wb,
    int Btot)
{
    int i = blockIdx.x * 8 + (threadIdx.x >> 5);
    int lane = threadIdx.x & 31;
    if (i >= Btot) return;
    {
        int o = clampi(obs[i], 0, NUM_OBS - 1);
        int a = clampi(act[i], 0, NUM_ACT - 1);
        long long idx = (long long)o * NUM_ACT + a;
        float2 v = *(const float2*)(Wf + idx * RD + lane * 2);
        *(__half2*)(g_F16 + i * RD + lane * 2) = __floats2half2_rn(v.x, v.y);
    }
    {
        int o = clampi(fobs[i], 0, NUM_OBS - 1);
        int a = clampi(fact[i], 0, NUM_ACT - 1);
        long long idx = (long long)o * NUM_ACT + a;
        float2 v = *(const float2*)(Wb + idx * RD + lane * 2);
        *(__half2*)(g_B16 + i * RD + lane * 2) = __floats2half2_rn(v.x, v.y);
    }
}

__device__ __forceinline__ uint32_t smem_u32(const void* p) {
    uint32_t a;
    asm("{ .reg .u64 t; cvta.to.shared.u64 t, %1; cvt.u32.u64 %0, t; }"
        : "=r"(a) : "l"(p));
    return a;
}

__device__ __forceinline__ void cp_async16(uint32_t dst, const void* src) {
    asm volatile("cp.async.cg.shared.global [%0], [%1], 16;"
                 :: "r"(dst), "l"(src));
}

__device__ __forceinline__ void ldsm_x4(uint32_t& r0, uint32_t& r1,
                                        uint32_t& r2, uint32_t& r3,
                                        uint32_t addr)
{
    asm volatile(
        "ldmatrix.sync.aligned.m8n8.x4.shared.b16 {%0,%1,%2,%3}, [%4];"
        : "=r"(r0), "=r"(r1), "=r"(r2), "=r"(r3)
        : "r"(addr));
}

__device__ __forceinline__ void mma16816_f16(float* c, const uint32_t* a,
                                             const uint32_t* b)
{
    asm volatile(
        "mma.sync.aligned.m16n8k16.row.col.f32.f16.f16.f32 "
        "{%0,%1,%2,%3}, {%4,%5,%6,%7}, {%8,%9}, {%0,%1,%2,%3};"
        : "+f"(c[0]), "+f"(c[1]), "+f"(c[2]), "+f"(c[3])
        : "r"(a[0]), "r"(a[1]), "r"(a[2]), "r"(a[3]),
          "r"(b[0]), "r"(b[1]));
}

__device__ __forceinline__ void stg_cs_128(float* p, float4 v) {
    asm volatile("st.global.cs.v4.f32 [%0], {%1,%2,%3,%4};"
                 :: "l"(p), "f"(v.x), "f"(v.y), "f"(v.z), "f"(v.w)
                 : "memory");
}

// out[i][j] = F[i].B[j], single-pass fp16 HMMA, fp32 accumulation.
// CTA tile 64x128, 8 warps of 32(M)x32(N), K=64 resident. Small smem (35KB)
// + <=64 regs -> 4 CTAs/SM so compute and store-burst phases overlap across CTAs.
__global__ void __launch_bounds__(THREADS, 4) fb_gemm_kernel(
    float* __restrict__ out, int Btot)
{
    extern __shared__ __align__(16) uint8_t smem[];
    const uint32_t sbase = smem_u32(smem);
    const int tid = threadIdx.x;
    const int tileM = blockIdx.y * BM;
    const int tileN = blockIdx.x * BN;

    // ---- fill smem via cp.async (SW128 swizzle: 16B chunk ^ (row&7)) ----
    {
        const uint4* srcA = (const uint4*)g_F16;  // 8 uint4 per 64-half row
        const uint4* srcB = (const uint4*)g_B16;
        // A: 512 chunks (64 rows x 8)
#pragma unroll
        for (int it = 0; it < 2; it++) {
            int t = tid + it * THREADS;       // 0..511
            int r = t >> 3, ch = t & 7;
            uint32_t soff = OFF_A + r * 128 + ((ch ^ (r & 7)) << 4);
            int ga = tileM + r;
            if (ga < Btot) cp_async16(sbase + soff, srcA + ga * 8 + ch);
            else *(uint4*)(smem + soff) = make_uint4(0u, 0u, 0u, 0u);
        }
        // B: 1024 chunks (128 rows x 8)
#pragma unroll
        for (int it = 0; it < 4; it++) {
            int t = tid + it * THREADS;       // 0..1023
            int r = t >> 3, ch = t & 7;
            uint32_t soff = OFF_B + r * 128 + ((ch ^ (r & 7)) << 4);
            int gb = tileN + r;
            if (gb < Btot) cp_async16(sbase + soff, srcB + gb * 8 + ch);
            else *(uint4*)(smem + soff) = make_uint4(0u, 0u, 0u, 0u);
        }
        asm volatile("cp.async.commit_group;");
        asm volatile("cp.async.wait_group 0;");
    }
    __syncthreads();

    const int wid = tid >> 5, lane = tid & 31;
    const int m0w = (wid & 1) * 32;   // 2 warps over M
    const int n0w = (wid >> 1) * 32;  // 4 warps over N

    // ldmatrix per-lane addressing: lanes in 4 groups of 8.
    const int lr = lane & 7;
    const int lq = lane >> 3;
    const int row_add = lr + (lq & 1) * 8;   // +8 rows for groups 1,3
    const int kb_add = (lq >> 1) * 16;       // +16 B (k+8) for groups 2,3
    const int swz = lr << 4;                 // SW128 xor: (row&7)<<4 == lr<<4

    float c[2][4][4];
#pragma unroll
    for (int mf = 0; mf < 2; mf++)
#pragma unroll
        for (int nf = 0; nf < 4; nf++)
#pragma unroll
            for (int r = 0; r < 4; r++) c[mf][nf][r] = 0.0f;

#pragma unroll
    for (int ks = 0; ks < 4; ks++) {
        int kb = ks * 32;  // byte offset within 128 B row
        uint32_t a[2][4];
#pragma unroll
        for (int mf = 0; mf < 2; mf++) {
            int row = m0w + mf * 16 + row_add;
            uint32_t addr = sbase + OFF_A + row * 128 + ((kb + kb_add) ^ swz);
            ldsm_x4(a[mf][0], a[mf][1], a[mf][2], a[mf][3], addr);
        }
        uint32_t b[4][2];
#pragma unroll
        for (int nh = 0; nh < 2; nh++) {
            int row = n0w + nh * 16 + row_add;
            uint32_t addr = sbase + OFF_B + row * 128 + ((kb + kb_add) ^ swz);
            uint32_t r0, r1, r2, r3;
            ldsm_x4(r0, r1, r2, r3, addr);
            b[nh * 2 + 0][0] = r0;
            b[nh * 2 + 1][0] = r1;
            b[nh * 2 + 0][1] = r2;
            b[nh * 2 + 1][1] = r3;
        }
#pragma unroll
        for (int mf = 0; mf < 2; mf++)
#pragma unroll
            for (int nf = 0; nf < 4; nf++)
                mma16816_f16(c[mf][nf], a[mf], b[nf]);
    }

    // ---- epilogue: stage C in smem (overlays dead operand region), then
    //      fully coalesced streaming STG.128 ----
    __syncthreads();  // operand smem dead from here; safe to overwrite
    {
        float* cs = (float*)smem;
        const int gid = lane >> 2, qid = lane & 3;
#pragma unroll
        for (int mf = 0; mf < 2; mf++) {
            int r0 = m0w + mf * 16 + gid;
#pragma unroll
            for (int nf = 0; nf < 4; nf++) {
                int col = n0w + nf * 8 + qid * 2;
                *(float2*)(cs + r0 * CSTRIDE + col) =
                    make_float2(c[mf][nf][0], c[mf][nf][1]);
                *(float2*)(cs + (r0 + 8) * CSTRIDE + col) =
                    make_float2(c[mf][nf][2], c[mf][nf][3]);
            }
        }
    }
    __syncthreads();
    {
        const float* cs = (const float*)smem;
#pragma unroll
        for (int i = 0; i < 8; i++) {
            int lrow = wid * 8 + i;           // 8 warps x 8 rows = 64 rows
            int grow = tileM + lrow;
            if (grow >= Btot) continue;
            float4 v = *(const float4*)(cs + lrow * CSTRIDE + lane * 4);
            int gcol = tileN + lane * 4;
            if (tileN + BN <= Btot) {
                stg_cs_128(out + (size_t)grow * Btot + gcol, v);
            } else {
                float vv[4] = { v.x, v.y, v.z, v.w };
                for (int j = 0; j < 4; j++)
                    if (gcol + j < Btot)
                        out[(size_t)grow * Btot + gcol + j] = vv[j];
            }
        }
    }
}

extern "C" void kernel_launch(void* const* d_in, const int* in_sizes, int n_in,
                              void* d_out, int out_size)
{
    const int* obs  = (const int*)d_in[0];
    const int* act  = (const int*)d_in[1];
    const int* fobs = (const int*)d_in[2];
    const int* fact = (const int*)d_in[3];
    const float* Wf = (const float*)d_in[4];
    const float* Wb = (const float*)d_in[5];
    float* out = (float*)d_out;
    int Btot = in_sizes[0];

    gather_kernel<<<(Btot + 7) / 8, 256>>>(obs, act, fobs, fact, Wf, Wb, Btot);

    cudaFuncSetAttribute(fb_gemm_kernel,
                         cudaFuncAttributeMaxDynamicSharedMemorySize,
                         SMEM_BYTES);
    dim3 grid((Btot + BN - 1) / BN, (Btot + BM - 1) / BM);
    fb_gemm_kernel<<<grid, THREADS, SMEM_BYTES>>>(out, Btot);
}